// round 3
// baseline (speedup 1.0000x reference)
#include <cuda_runtime.h>
#include <cuda_fp16.h>
#include <mma.h>

using namespace nvcuda;

#define T_STEPS 256
#define BATCH   64
#define LAYERS  4
#define HID     1024
#define KDIM    2048   // IN + H
#define NDIM    2048   // 2H

// ---------------- device global scratch (no allocations allowed) ----------------
__device__ __half g_Wr[LAYERS * KDIM * NDIM];      // fp16 weights, column-paired layout:
                                                   // [(l*32+s)*2048 + k][64], cols 0..31 = learn(s*32..), 32..63 = forget
__device__ float  g_br[LAYERS * NDIM];             // bias, same column pairing
__device__ __half g_X16[T_STEPS * BATCH * 1024];   // x in fp16
__device__ __half g_h16[LAYERS * BATCH * HID];     // hidden states fp16 (GEMM operand)
__device__ __half g_inp16[BATCH * HID];            // inter-layer activation fp16
__device__ float  g_hf[LAYERS * BATCH * HID];      // hidden states fp32 (gate recurrence)
__device__ float  g_zpart[4 * 32 * 64 * 64];       // K-split partial sums [ki][s][64 rows][64 cols]
__device__ unsigned g_count;
__device__ volatile unsigned g_phase;

// ---------------- helpers ----------------
__device__ __forceinline__ void cp16(void* sdst, const void* gsrc) {
    unsigned sa = (unsigned)__cvta_generic_to_shared(sdst);
    asm volatile("cp.async.cg.shared.global [%0], [%1], 16;" :: "r"(sa), "l"(gsrc));
}
__device__ __forceinline__ void cp_commit() { asm volatile("cp.async.commit_group;" ::: "memory"); }
template <int N>
__device__ __forceinline__ void cp_wait() { asm volatile("cp.async.wait_group %0;" :: "n"(N) : "memory"); }

__device__ __forceinline__ void gsync(unsigned& lp) {
    __syncthreads();
    if (threadIdx.x == 0) {
        lp++;
        __threadfence();
        unsigned old = atomicAdd(&g_count, 1);
        if (old == gridDim.x - 1) {
            g_count = 0;
            __threadfence();
            g_phase = lp;
        } else {
            while (g_phase < lp) {}
        }
    }
    __syncthreads();
}

// ---------------- prep kernels ----------------
__global__ void prep_weights(const float* __restrict__ W, const float* __restrict__ b) {
    long long idx0 = (long long)blockIdx.x * 256 + threadIdx.x;
    if (idx0 == 0) { g_count = 0; g_phase = 0; }
    if (idx0 < (long long)LAYERS * NDIM) {
        int l = (int)(idx0 / NDIM), n = (int)(idx0 % NDIM);
        int s, c;
        if (n < HID) { s = n >> 5; c = n & 31; }
        else         { s = (n - HID) >> 5; c = 32 + ((n - HID) & 31); }
        g_br[(l * 32 + s) * 64 + c] = b[idx0];
    }
    const long long total = (long long)LAYERS * KDIM * NDIM;
    for (long long i = idx0; i < total; i += (long long)gridDim.x * 256) {
        int n = (int)(i & (NDIM - 1));
        int k = (int)((i >> 11) & (KDIM - 1));
        int l = (int)(i >> 22);
        int s, c;
        if (n < HID) { s = n >> 5; c = n & 31; }
        else         { s = (n - HID) >> 5; c = 32 + ((n - HID) & 31); }
        g_Wr[(((size_t)(l * 32 + s) * 2048 + k) << 6) + c] = __float2half(W[i]);
    }
}

__global__ void prep_states(const float* __restrict__ x, const float* __restrict__ h) {
    long long idx = (long long)blockIdx.x * 256 + threadIdx.x;
    if (idx < (long long)LAYERS * BATCH * HID) {
        float v = h[idx];
        g_hf[idx]  = v;
        g_h16[idx] = __float2half(v);
    }
    const long long total = (long long)T_STEPS * BATCH * 1024;
    for (long long i = idx; i < total; i += (long long)gridDim.x * 256)
        g_X16[i] = __float2half(x[i]);
}

// ---------------- main persistent kernel ----------------
__global__ void __launch_bounds__(256, 1) rnn_persistent(float* __restrict__ out) {
    const int tid  = threadIdx.x;
    const int work = blockIdx.x;
    const bool active = work < 128;
    const int s  = work >> 2;     // h-slice (32 columns of H)
    const int ki = work & 3;      // K-split (512 of 2048)
    const int warp = tid >> 5;
    const int mi = warp >> 1;     // m-tile 0..3
    const int nh = warp & 1;      // n-half 0..1
    unsigned lp = 0;

    __shared__ __half As[2][64][72];
    __shared__ __half Ws[2][64][72];

    for (int t = 0; t < T_STEPS; ++t) {
        for (int l = 0; l < LAYERS; ++l) {
            // ---------- phase 1: partial GEMM ----------
            if (active) {
                wmma::fragment<wmma::accumulator, 16, 16, 16, float> acc0, acc1;
                wmma::fill_fragment(acc0, 0.f);
                wmma::fill_fragment(acc1, 0.f);

                const __half* Asrc;
                int koff;
                if (ki < 2) {
                    Asrc = (l == 0) ? (g_X16 + (size_t)t * (BATCH * 1024)) : g_inp16;
                    koff = ki * 512;
                } else {
                    Asrc = g_h16 + (size_t)l * (BATCH * HID);
                    koff = (ki - 2) * 512;
                }
                const __half* Wsrc = g_Wr + ((size_t)(l * 32 + s) << 17) + ((size_t)ki << 15);

                auto load_chunk = [&](int ch) {
                    int buf = ch & 1;
#pragma unroll
                    for (int rep = 0; rep < 2; ++rep) {
                        int i = tid + rep * 256;
                        int r = i >> 3, c8 = i & 7;
                        cp16(&As[buf][r][c8 * 8], Asrc + (size_t)r * 1024 + koff + ch * 64 + c8 * 8);
                        cp16(&Ws[buf][r][c8 * 8], Wsrc + ((size_t)ch << 12) + (size_t)i * 8);
                    }
                    cp_commit();
                };

                load_chunk(0);
#pragma unroll 1
                for (int ch = 0; ch < 8; ++ch) {
                    if (ch < 7) { load_chunk(ch + 1); cp_wait<1>(); }
                    else        { cp_wait<0>(); }
                    __syncthreads();
                    const int buf = ch & 1;
#pragma unroll
                    for (int kk = 0; kk < 4; ++kk) {
                        wmma::fragment<wmma::matrix_a, 16, 16, 16, __half, wmma::row_major> af;
                        wmma::load_matrix_sync(af, &As[buf][mi * 16][kk * 16], 72);
                        wmma::fragment<wmma::matrix_b, 16, 16, 16, __half, wmma::row_major> bf;
                        wmma::load_matrix_sync(bf, &Ws[buf][kk * 16][nh * 32], 72);
                        wmma::mma_sync(acc0, af, bf, acc0);
                        wmma::load_matrix_sync(bf, &Ws[buf][kk * 16][nh * 32 + 16], 72);
                        wmma::mma_sync(acc1, af, bf, acc1);
                    }
                    __syncthreads();
                }
                float* zb = g_zpart + ((size_t)(ki * 32 + s) << 12) + (mi * 16) * 64 + nh * 32;
                wmma::store_matrix_sync(zb, acc0, 64, wmma::mem_row_major);
                wmma::store_matrix_sync(zb + 16, acc1, 64, wmma::mem_row_major);
            }
            gsync(lp);

            // ---------- phase 2: K-reduce + gate (ki==0 blocks own both learn & forget cols) ----------
            if (active && ki == 0) {
                const int j  = tid & 31;
                const int w8 = tid >> 5;
                const int jg = (s << 5) + j;
                const float bl  = g_br[(l * 32 + s) * 64 + j];
                const float bfo = g_br[(l * 32 + s) * 64 + 32 + j];
#pragma unroll 1
                for (int rr = 0; rr < 8; ++rr) {
                    int r = w8 + rr * 8;
                    float zl = bl, zf = bfo;
#pragma unroll
                    for (int kk = 0; kk < 4; ++kk) {
                        const float* zp = g_zpart + ((size_t)kk << 17) + ((size_t)s << 12) + r * 64;
                        zl += __ldcg(zp + j);
                        zf += __ldcg(zp + 32 + j);
                    }
                    int hidx = l * (BATCH * HID) + r * HID + jg;
                    float hp = g_hf[hidx];
                    float f  = 1.f / (1.f + __expf(-zf));
                    float hn = fmaf(f, hp, (1.f - f) * tanhf(zl));
                    g_hf[hidx]  = hn;
                    __half hh   = __float2half(hn);
                    g_h16[hidx] = hh;
                    if (l < 3) g_inp16[r * HID + jg] = hh;
                    else       out[((size_t)(t * 64 + r) << 10) + jg] = hn;
                }
            }
            gsync(lp);
        }
    }

    // ---------- h_final: [L*B, H] appended after outputs ----------
    for (int i = blockIdx.x * 256 + tid; i < LAYERS * BATCH * HID; i += gridDim.x * 256)
        out[(size_t)T_STEPS * BATCH * HID + i] = __ldcg(&g_hf[i]);
}

// ---------------- launch ----------------
extern "C" void kernel_launch(void* const* d_in, const int* in_sizes, int n_in,
                              void* d_out, int out_size) {
    const float* x = (const float*)d_in[0];
    const float* h = (const float*)d_in[1];
    const float* W = (const float*)d_in[2];
    const float* b = (const float*)d_in[3];
    float* out = (float*)d_out;

    int dev = 0;
    cudaGetDevice(&dev);
    int nsm = 148;
    cudaDeviceGetAttribute(&nsm, cudaDevAttrMultiProcessorCount, dev);
    if (nsm < 128) nsm = 128;  // persistent grid needs >= 128 working blocks

    prep_weights<<<4096, 256>>>(W, b);
    prep_states<<<4096, 256>>>(x, h);
    rnn_persistent<<<nsm, 256>>>(out);
}

// round 4
// speedup vs baseline: 2.6262x; 2.6262x over previous
#include <cuda_runtime.h>
#include <cuda_fp16.h>
#include <mma.h>

using namespace nvcuda;

#define T_STEPS 256
#define BATCH   64
#define LAYERS  4
#define HID     1024
#define KDIM    2048   // IN + H
#define NDIM    2048   // 2H

// ---------------- device global scratch (no allocations allowed) ----------------
__device__ __half g_Wr[LAYERS * KDIM * NDIM];        // [(l*32+s)*2048 + k][64] paired cols: 0..31 learn, 32..63 forget
__device__ float  g_br[LAYERS * NDIM];               // bias, same pairing
__device__ __half g_X16[T_STEPS * BATCH * 1024];     // x in fp16 (layer-0 input)
__device__ __half g_act[3u * T_STEPS * BATCH * HID]; // inter-layer activations, depth-T (no backpressure)
__device__ __half g_h16[LAYERS * BATCH * HID];       // hidden fp16 (GEMM operand)
__device__ float  g_hf[LAYERS * BATCH * HID];        // hidden fp32 (gate recurrence)
__device__ unsigned g_done[LAYERS * T_STEPS];        // per-(layer, t) completion counters

// ---------------- helpers ----------------
__device__ __forceinline__ void cp16(void* sdst, const void* gsrc) {
    unsigned sa = (unsigned)__cvta_generic_to_shared(sdst);
    asm volatile("cp.async.cg.shared.global [%0], [%1], 16;" :: "r"(sa), "l"(gsrc));
}
__device__ __forceinline__ void cp_commit() { asm volatile("cp.async.commit_group;" ::: "memory"); }
template <int N>
__device__ __forceinline__ void cp_wait() { asm volatile("cp.async.wait_group %0;" :: "n"(N) : "memory"); }

__device__ __forceinline__ void spin_ge(const unsigned* p, unsigned v) {
    unsigned x;
    do {
        asm volatile("ld.acquire.gpu.global.u32 %0, [%1];" : "=r"(x) : "l"(p) : "memory");
    } while (x < v);
}

// ---------------- prep kernels ----------------
__global__ void prep_weights(const float* __restrict__ W, const float* __restrict__ b) {
    long long idx0 = (long long)blockIdx.x * 256 + threadIdx.x;
    if (idx0 < LAYERS * T_STEPS) g_done[idx0] = 0;
    if (idx0 < (long long)LAYERS * NDIM) {
        int l = (int)(idx0 / NDIM), n = (int)(idx0 % NDIM);
        int s, c;
        if (n < HID) { s = n >> 5; c = n & 31; }
        else         { s = (n - HID) >> 5; c = 32 + ((n - HID) & 31); }
        g_br[(l * 32 + s) * 64 + c] = b[idx0];
    }
    const long long total = (long long)LAYERS * KDIM * NDIM;
    for (long long i = idx0; i < total; i += (long long)gridDim.x * 256) {
        int n = (int)(i & (NDIM - 1));
        int k = (int)((i >> 11) & (KDIM - 1));
        int l = (int)(i >> 22);
        int s, c;
        if (n < HID) { s = n >> 5; c = n & 31; }
        else         { s = (n - HID) >> 5; c = 32 + ((n - HID) & 31); }
        g_Wr[(((size_t)(l * 32 + s) * 2048 + k) << 6) + c] = __float2half(W[i]);
    }
}

__global__ void prep_states(const float* __restrict__ x, const float* __restrict__ h) {
    long long idx = (long long)blockIdx.x * 256 + threadIdx.x;
    if (idx < (long long)LAYERS * BATCH * HID) {
        float v = h[idx];
        g_hf[idx]  = v;
        g_h16[idx] = __float2half(v);
    }
    const long long total = (long long)T_STEPS * BATCH * 1024;
    for (long long i = idx; i < total; i += (long long)gridDim.x * 256)
        g_X16[i] = __float2half(x[i]);
}

// ---------------- main persistent kernel: layer-wavefront ----------------
// Grid = 128 blocks: 4 layer groups x 32 column-slice blocks. Each block computes
// the FULL K=2048 GEMM for its 64 paired output columns, then the gate, in-block.
// Cross-stage deps are point-to-point acquire/release flags, no grid barriers.
__global__ void __launch_bounds__(256, 1) rnn_persistent(float* __restrict__ out) {
    extern __shared__ __align__(16) unsigned char dynsmem[];
    // layout: As[4][64][72] halfs | Ws[4][64][72] halfs | zs[64][68] floats
    __half* As_base = (__half*)dynsmem;
    __half* Ws_base = As_base + 4 * 64 * 72;
    float*  zs      = (float*)(dynsmem + 2 * (4 * 64 * 72) * sizeof(__half));

    const int tid  = threadIdx.x;
    const int l    = blockIdx.x >> 5;   // layer group 0..3
    const int s    = blockIdx.x & 31;   // column-slice 0..31
    const int warp = tid >> 5;
    const int mi   = warp >> 1;         // m-tile 0..3 (16 rows each)
    const int nh   = warp & 1;          // n-half 0..1 (32 cols each)
    const int j    = tid & 31;          // gate column within slice
    const int w8   = tid >> 5;          // gate row base

    const __half* Wbase = g_Wr + ((size_t)(l * 32 + s) << 17);          // 2048*64 halfs
    const __half* hbase = g_h16 + (size_t)l * (BATCH * HID);
    const __half* ibase0 = (l == 0) ? g_X16
                                    : (g_act + (size_t)(l - 1) * T_STEPS * BATCH * HID);
    const float bl  = g_br[(l * 32 + s) * 64 + j];
    const float bfo = g_br[(l * 32 + s) * 64 + 32 + j];
    const int jg = (s << 5) + j;

    for (int t = 0; t < T_STEPS; ++t) {
        // ---- wait for producers: inp from layer l-1 at t, own h (whole group) from t-1 ----
        if (tid == 0) {
            if (l > 0) spin_ge(&g_done[(l - 1) * T_STEPS + t], 32);
            if (t > 0) spin_ge(&g_done[l * T_STEPS + t - 1], 32);
        }
        __syncthreads();

        const __half* ibase = ibase0 + (size_t)t * (BATCH * 1024);

        wmma::fragment<wmma::accumulator, 16, 16, 16, float> acc0, acc1;
        wmma::fill_fragment(acc0, 0.f);
        wmma::fill_fragment(acc1, 0.f);

        auto load_chunk = [&](int ch) {
            const int slot = ch & 3;
            const __half* asrc;
            int kb;
            if (ch < 16) { asrc = ibase; kb = ch * 64; }
            else         { asrc = hbase; kb = (ch - 16) * 64; }
            __half* as = As_base + slot * (64 * 72);
            __half* ws = Ws_base + slot * (64 * 72);
#pragma unroll
            for (int rep = 0; rep < 2; ++rep) {
                int i = tid + rep * 256;
                int r = i >> 3, c8 = i & 7;
                cp16(as + r * 72 + c8 * 8, asrc + (size_t)r * 1024 + kb + c8 * 8);
                cp16(ws + r * 72 + c8 * 8, Wbase + (((size_t)(ch * 64 + r)) << 6) + c8 * 8);
            }
            cp_commit();
        };

        // ---- 4-deep pipelined GEMM over K=2048 (32 chunks of 64) ----
        load_chunk(0); load_chunk(1); load_chunk(2);
#pragma unroll 4
        for (int ch = 0; ch < 32; ++ch) {
            if (ch < 29)      cp_wait<2>();   // chunk ch complete (2 newer may be in flight)
            else if (ch == 29) cp_wait<2>();
            else if (ch == 30) cp_wait<1>();
            else               cp_wait<0>();
            __syncthreads();                  // all threads' copies for chunk ch visible;
                                              // also protects slot reuse (distance-4 ring, issue 3 ahead)
            const int slot = ch & 3;
            const __half* as = As_base + slot * (64 * 72);
            const __half* ws = Ws_base + slot * (64 * 72);
#pragma unroll
            for (int kk = 0; kk < 4; ++kk) {
                wmma::fragment<wmma::matrix_a, 16, 16, 16, __half, wmma::row_major> af;
                wmma::load_matrix_sync(af, as + (mi * 16) * 72 + kk * 16, 72);
                wmma::fragment<wmma::matrix_b, 16, 16, 16, __half, wmma::row_major> bf;
                wmma::load_matrix_sync(bf, ws + (kk * 16) * 72 + nh * 32, 72);
                wmma::mma_sync(acc0, af, bf, acc0);
                wmma::load_matrix_sync(bf, ws + (kk * 16) * 72 + nh * 32 + 16, 72);
                wmma::mma_sync(acc1, af, bf, acc1);
            }
            if (ch < 29) load_chunk(ch + 3);  // issued after compute; next write of this
                                              // slot is gated by iteration ch+1's barrier
        }

        // ---- z -> smem (learn/forget halves live in different warps) ----
        {
            float* zb = zs + (mi * 16) * 68 + nh * 32;
            wmma::store_matrix_sync(zb,      acc0, 68, wmma::mem_row_major);
            wmma::store_matrix_sync(zb + 16, acc1, 68, wmma::mem_row_major);
        }
        __syncthreads();

        // ---- fused gate: 8 rows per thread ----
#pragma unroll
        for (int rr = 0; rr < 8; ++rr) {
            int r = w8 + rr * 8;
            float zl = bl  + zs[r * 68 + j];
            float zf = bfo + zs[r * 68 + 32 + j];
            int hidx = l * (BATCH * HID) + r * HID + jg;
            float hp = g_hf[hidx];
            float f  = 1.f / (1.f + __expf(-zf));
            float hn = fmaf(f, hp, (1.f - f) * tanhf(zl));
            g_hf[hidx]  = hn;
            __half hh   = __float2half(hn);
            g_h16[hidx] = hh;
            if (l < 3) g_act[((size_t)l * T_STEPS + t) * (BATCH * 1024) + r * 1024 + jg] = hh;
            else       out[((size_t)(t * 64 + r) << 10) + jg] = hn;
        }
        __syncthreads();   // all gate writes issued before the release below

        if (tid == 0) {
            __threadfence();
            atomicAdd(&g_done[l * T_STEPS + t], 1u);
        }
    }

    // ---- h_final: each block copies only data it wrote itself (no sync needed) ----
#pragma unroll
    for (int rr = 0; rr < 8; ++rr) {
        int r = w8 + rr * 8;
        int idx = l * (BATCH * HID) + r * HID + jg;
        out[(size_t)T_STEPS * BATCH * HID + idx] = g_hf[idx];
    }
}

// ---------------- launch ----------------
extern "C" void kernel_launch(void* const* d_in, const int* in_sizes, int n_in,
                              void* d_out, int out_size) {
    const float* x = (const float*)d_in[0];
    const float* h = (const float*)d_in[1];
    const float* W = (const float*)d_in[2];
    const float* b = (const float*)d_in[3];
    float* out = (float*)d_out;

    // dyn smem: As/Ws rings (73728 B) + z staging (64*68*4 = 17408 B)
    const int dynsmem = 2 * (4 * 64 * 72) * (int)sizeof(__half) + 64 * 68 * (int)sizeof(float);
    static int attr_set = 0;
    if (!attr_set) {
        cudaFuncSetAttribute(rnn_persistent, cudaFuncAttributeMaxDynamicSharedMemorySize, dynsmem);
        attr_set = 1;
    }

    prep_weights<<<4096, 256>>>(W, b);
    prep_states<<<4096, 256>>>(x, h);
    rnn_persistent<<<128, 256, dynsmem>>>(out);
}

// round 12
// speedup vs baseline: 3.7267x; 1.4191x over previous
#include <cuda_runtime.h>
#include <cuda_fp16.h>
#include <mma.h>
#include <cstdint>

using namespace nvcuda;

#define NT    256
#define NB    64
#define NLAY  4
#define NHID  1024
#define NCH   16       // K chunks of 128 halfs per stage (K = 2048)

// ---------------- device global scratch ----------------
__device__ __half   g_W[(size_t)NLAY * 32 * 2048 * 64];   // [(l*32+s)*2048 + k][64]; cols 0-31 learn, 32-63 forget
__device__ float    g_br[NLAY * 2048];                    // bias, paired cols
__device__ __half   g_X[(size_t)NT * NB * 1024];          // x fp16, plain [t][r][k]
__device__ __half   g_act[(size_t)NLAY * 257 * NB * 1024];// [l][slot][r][jg]; slot0 = h_init, slot t+1 = h(t)
__device__ unsigned g_done[NLAY * NT];

// ---------------- helpers ----------------
__device__ __forceinline__ void cp16(uint32_t sdst, const void* gsrc) {
    asm volatile("cp.async.cg.shared.global [%0], [%1], 16;" :: "r"(sdst), "l"(gsrc));
}
// .noinc is load-bearing: the default form is count-neutral (inc at issue, dec at
// completion) and deadlocks a barrier whose only arrivals are cp.async-tracked.
__device__ __forceinline__ void cp_mbar_arrive(uint32_t mbar) {
    asm volatile("cp.async.mbarrier.arrive.noinc.shared.b64 [%0];" :: "r"(mbar) : "memory");
}
__device__ __forceinline__ void mbar_init(uint32_t a, uint32_t cnt) {
    asm volatile("mbarrier.init.shared.b64 [%0], %1;" :: "r"(a), "r"(cnt) : "memory");
}
__device__ __forceinline__ void mbar_arrive(uint32_t a) {
    asm volatile("mbarrier.arrive.shared.b64 _, [%0];" :: "r"(a) : "memory");
}
__device__ __forceinline__ void mbar_wait(uint32_t a, uint32_t parity) {
    asm volatile(
        "{\n\t.reg .pred P;\n\tWL_%=: \n\t"
        "mbarrier.try_wait.parity.acquire.cta.shared::cta.b64 P, [%0], %1, 0x989680;\n\t"
        "@P bra.uni WD_%=;\n\tbra.uni WL_%=;\n\tWD_%=: \n\t}"
        :: "r"(a), "r"(parity) : "memory");
}
__device__ __forceinline__ void spin_ge(const unsigned* p, unsigned v) {
    unsigned x;
    do { asm volatile("ld.acquire.gpu.global.u32 %0, [%1];" : "=r"(x) : "l"(p) : "memory"); } while (x < v);
}
__device__ __forceinline__ float tanh_fast(float x) {
    float y; asm("tanh.approx.f32 %0, %1;" : "=f"(y) : "f"(x)); return y;
}

// ---------------- prep kernels ----------------
__global__ void prep_weights(const float* __restrict__ W, const float* __restrict__ b) {
    long long i0 = (long long)blockIdx.x * 256 + threadIdx.x;
    if (i0 < NLAY * NT) g_done[i0] = 0;
    if (i0 < NLAY * 2048) {
        int l = (int)(i0 >> 11), n = (int)(i0 & 2047);
        int s, c;
        if (n < NHID) { s = n >> 5; c = n & 31; }
        else          { s = (n - NHID) >> 5; c = 32 + ((n - NHID) & 31); }
        g_br[(l * 32 + s) * 64 + c] = b[i0];
    }
    const long long total = (long long)NLAY * 2048 * 2048;
    for (long long i = i0; i < total; i += (long long)gridDim.x * 256) {
        int n = (int)(i & 2047);
        int k = (int)((i >> 11) & 2047);
        int l = (int)(i >> 22);
        int s, c;
        if (n < NHID) { s = n >> 5; c = n & 31; }
        else          { s = (n - NHID) >> 5; c = 32 + ((n - NHID) & 31); }
        g_W[(((size_t)(l * 32 + s) * 2048 + k) << 6) + c] = __float2half(W[i]);
    }
}

__global__ void prep_states(const float* __restrict__ x, const float* __restrict__ h) {
    long long i0 = (long long)blockIdx.x * 256 + threadIdx.x;
    if (i0 < (long long)NLAY * NB * NHID) {   // h -> act[l][slot 0]
        int l = (int)(i0 >> 16);
        g_act[(size_t)l * 257 * 65536 + (i0 & 65535)] = __float2half(h[i0]);
    }
    const long long total = (long long)NT * NB * 1024;
    for (long long i = i0; i < total; i += (long long)gridDim.x * 256)
        g_X[i] = __float2half(x[i]);
}

// ---------------- main persistent kernel ----------------
// 128 blocks = 4 layers x 32 slices (64 paired cols each). 256 threads:
//   warps 0-3: wmma compute (32x32 tiles), warps 4-7: cp.async producer + gate.
#define AS_B  17408   // 64 x 136 halfs
#define WS_B  18432   // 128 x 72 halfs

__global__ void __launch_bounds__(256, 1) rnn_persistent(float* __restrict__ out, const float* __restrict__ h0) {
    extern __shared__ __align__(16) unsigned char dynsmem[];
    const uint32_t raw  = (uint32_t)__cvta_generic_to_shared(dynsmem);
    const uint32_t base = (raw + 1023u) & ~1023u;
    const uint32_t goff = base - raw;                 // generic-pointer offset of base

    const uint32_t full_mb  = base + 0;               // 4 x 8B
    const uint32_t free_mb  = base + 32;              // 4 x 8B
    const uint32_t zdone_mb = base + 64;              // 2 x 8B
    const uint32_t zfree_mb = base + 80;              // 2 x 8B
    const uint32_t As0 = base + 1024;                 // 4 x AS_B
    const uint32_t Ws0 = As0 + 4 * AS_B;              // 4 x WS_B
    __half* As_gen = (__half*)(dynsmem + goff + 1024);
    __half* Ws_gen = (__half*)(dynsmem + goff + 1024 + 4 * AS_B);
    float*  zbuf   = (float*)(dynsmem + goff + 1024 + 4 * AS_B + 4 * WS_B);  // 2 x 64 x 68

    const int tid = threadIdx.x;
    const int wid = tid >> 5;
    const int l = blockIdx.x >> 5;
    const int s = blockIdx.x & 31;

    if (tid == 0) {
        for (int i = 0; i < 4; ++i) { mbar_init(full_mb + i * 8, 128); mbar_init(free_mb + i * 8, 128); }
        mbar_init(zdone_mb, 128); mbar_init(zdone_mb + 8, 128);
        mbar_init(zfree_mb, 128); mbar_init(zfree_mb + 8, 128);
    }
    __syncthreads();

    if (wid < 4) {
        // ================= compute: warps 0-3, 32x32 output tiles =================
        const int mi = wid >> 1, ni = wid & 1;
        unsigned c = 0;
        for (int t = 0; t < NT; ++t) {
            wmma::fragment<wmma::accumulator, 16, 16, 16, float> acc[2][2];
#pragma unroll
            for (int i = 0; i < 2; ++i)
#pragma unroll
                for (int jj = 0; jj < 2; ++jj) wmma::fill_fragment(acc[i][jj], 0.f);

            for (int ch = 0; ch < NCH; ++ch, ++c) {
                const int slot = c & 3;
                const unsigned u = c >> 2;
                mbar_wait(full_mb + slot * 8, u & 1);
                const __half* as = As_gen + slot * (AS_B / 2);
                const __half* ws = Ws_gen + slot * (WS_B / 2);
#pragma unroll
                for (int kk = 0; kk < 8; ++kk) {
                    wmma::fragment<wmma::matrix_a, 16, 16, 16, __half, wmma::row_major> af0, af1;
                    wmma::fragment<wmma::matrix_b, 16, 16, 16, __half, wmma::row_major> bf0, bf1;
                    wmma::load_matrix_sync(af0, as + (mi * 32) * 136 + kk * 16, 136);
                    wmma::load_matrix_sync(af1, as + (mi * 32 + 16) * 136 + kk * 16, 136);
                    wmma::load_matrix_sync(bf0, ws + (kk * 16) * 72 + ni * 32, 72);
                    wmma::load_matrix_sync(bf1, ws + (kk * 16) * 72 + ni * 32 + 16, 72);
                    wmma::mma_sync(acc[0][0], af0, bf0, acc[0][0]);
                    wmma::mma_sync(acc[0][1], af0, bf1, acc[0][1]);
                    wmma::mma_sync(acc[1][0], af1, bf0, acc[1][0]);
                    wmma::mma_sync(acc[1][1], af1, bf1, acc[1][1]);
                }
                mbar_arrive(free_mb + slot * 8);
            }
            if (t >= 2) mbar_wait(zfree_mb + (t & 1) * 8, ((t - 2) >> 1) & 1);
            float* z = zbuf + (t & 1) * (64 * 68);
#pragma unroll
            for (int i = 0; i < 2; ++i)
#pragma unroll
                for (int jj = 0; jj < 2; ++jj)
                    wmma::store_matrix_sync(z + (mi * 32 + i * 16) * 68 + ni * 32 + jj * 16,
                                            acc[i][jj], 68, wmma::mem_row_major);
            mbar_arrive(zdone_mb + (t & 1) * 8);
        }
    } else {
        // ================= producer + gate: warps 4-7 =================
        const int pid = tid - 128;                    // 0..127
        const int r   = pid >> 1;                     // gate row 0..63
        const int hf  = pid & 1;                      // col half
        const int j0  = hf * 16;
        const int jg0 = s * 32 + j0;
        const __half* Wbase = g_W + ((size_t)(l * 32 + s) << 17);

        float hreg[16], blv[16], bfv[16];
#pragma unroll
        for (int i = 0; i < 16; ++i) {
            blv[i]  = g_br[(l * 32 + s) * 64 + j0 + i];
            bfv[i]  = g_br[(l * 32 + s) * 64 + 32 + j0 + i];
            hreg[i] = h0[(size_t)(l * 64 + r) * 1024 + jg0 + i];
        }

        unsigned c = 0;
        auto produce = [&](const __half* asrc, int ch) {
            const int slot = c & 3;
            const unsigned u = c >> 2;
            if (u > 0) mbar_wait(free_mb + slot * 8, (u - 1) & 1);
            // A-side K offset within the 1024-wide source row: chunks 0-7 read the
            // x/input source, chunks 8-15 read the h source. BOTH are 1024-wide
            // images starting at K-offset 0, so the A offset is (ch & 7) * 128.
            // (Passing raw ch*128 for h chunks read row ar+1 -> R8/R9 rel_err 0.5.)
            const int aoff = (ch & 7) * 128;
#pragma unroll
            for (int k8 = 0; k8 < 8; ++k8) {          // A: 64 x 128 halfs
                int i = pid + k8 * 128;
                int ar = i >> 4, c16 = i & 15;
                cp16(As0 + slot * AS_B + (ar * 136 + c16 * 8) * 2,
                     asrc + (size_t)ar * 1024 + aoff + c16 * 8);
            }
            // W-side: ch indexes the full K=2048 range directly (rows 0-1023 input
            // weights, rows 1024-2047 hidden weights).
#pragma unroll
            for (int k8 = 0; k8 < 8; ++k8) {          // W: 128 x 64 halfs
                int i = pid + k8 * 128;
                int wr = i >> 3, c8 = i & 7;
                cp16(Ws0 + slot * WS_B + (wr * 72 + c8 * 8) * 2,
                     Wbase + (((size_t)(ch * 128 + wr)) << 6) + c8 * 8);
            }
            cp_mbar_arrive(full_mb + slot * 8);
            ++c;
        };
        auto produce_x = [&](int t) {                 // chunks 0-7: layer input at time t
            const __half* asrc = (l == 0) ? (g_X + (size_t)t * 65536)
                                          : (g_act + (((size_t)(l - 1) * 257 + t + 1) << 16));
            if (l > 0) spin_ge(&g_done[(l - 1) * NT + t], 32);
            for (int ch = 0; ch < 8; ++ch) produce(asrc, ch);
        };
        auto produce_h = [&](int t) {                 // chunks 8-15: h(t-1) = act[l][slot t]
            // Full 1024-wide K operand carries contributions from ALL 32
            // slice-blocks of this layer -> wait for the whole layer's gate at t-1.
            if (t > 0) spin_ge(&g_done[l * NT + t - 1], 32);
            const __half* asrc = g_act + (((size_t)l * 257 + t) << 16);
            for (int ch = 8; ch < 16; ++ch) produce(asrc, ch);
        };

        produce_x(0); produce_h(0);
        for (int t = 0; t < NT; ++t) {
            if (t + 1 < NT) produce_x(t + 1);         // overlap next stage's x-half with this gate

            mbar_wait(zdone_mb + (t & 1) * 8, (t >> 1) & 1);
            const float* z = zbuf + (t & 1) * (64 * 68);
            float zl[16], zf[16];
#pragma unroll
            for (int i = 0; i < 16; ++i) { zl[i] = z[r * 68 + j0 + i]; zf[i] = z[r * 68 + 32 + j0 + i]; }
            mbar_arrive(zfree_mb + (t & 1) * 8);      // z buffer free for stage t+2

            __half* act = g_act + (((size_t)l * 257 + t + 1) << 16) + r * 1024 + jg0;
            float hv[16];
#pragma unroll
            for (int i = 0; i < 8; ++i) {
                float f0 = 1.f / (1.f + __expf(-(zf[2 * i]     + bfv[2 * i])));
                float f1 = 1.f / (1.f + __expf(-(zf[2 * i + 1] + bfv[2 * i + 1])));
                float h0v = fmaf(f0, hreg[2 * i],     (1.f - f0) * tanh_fast(zl[2 * i]     + blv[2 * i]));
                float h1v = fmaf(f1, hreg[2 * i + 1], (1.f - f1) * tanh_fast(zl[2 * i + 1] + blv[2 * i + 1]));
                hreg[2 * i] = h0v; hreg[2 * i + 1] = h1v;
                hv[2 * i] = h0v; hv[2 * i + 1] = h1v;
                *(__half2*)(act + 2 * i) = __halves2half2(__float2half(h0v), __float2half(h1v));
            }
            if (l == 3) {
                float4* ob = (float4*)(out + (size_t)(t * 64 + r) * 1024 + jg0);
#pragma unroll
                for (int q = 0; q < 4; ++q)
                    ob[q] = make_float4(hv[4 * q], hv[4 * q + 1], hv[4 * q + 2], hv[4 * q + 3]);
            }
            asm volatile("bar.sync 1, 128;" ::: "memory");   // gate warps only
            if (pid == 0) { __threadfence(); atomicAdd(&g_done[l * NT + t], 1u); }

            if (t + 1 < NT) produce_h(t + 1);         // waits whole-layer done(t) inside
        }
        // h_final appended after outputs
        float4* ob = (float4*)(out + (size_t)NT * NB * NHID + (size_t)(l * 64 + r) * 1024 + jg0);
#pragma unroll
        for (int q = 0; q < 4; ++q)
            ob[q] = make_float4(hreg[4 * q], hreg[4 * q + 1], hreg[4 * q + 2], hreg[4 * q + 3]);
    }
}

// ---------------- launch ----------------
extern "C" void kernel_launch(void* const* d_in, const int* in_sizes, int n_in,
                              void* d_out, int out_size) {
    const float* x = (const float*)d_in[0];
    const float* h = (const float*)d_in[1];
    const float* W = (const float*)d_in[2];
    const float* b = (const float*)d_in[3];
    float* out = (float*)d_out;

    // dyn smem: 1024 align slack + 1024 mbars + 4*AS_B + 4*WS_B + 2*64*68*4
    const int dynsmem = 1024 + 1024 + 4 * AS_B + 4 * WS_B + 2 * 64 * 68 * 4;  // 180224
    static int attr_set = 0;
    if (!attr_set) {
        cudaFuncSetAttribute(rnn_persistent, cudaFuncAttributeMaxDynamicSharedMemorySize, dynsmem);
        attr_set = 1;
    }

    prep_weights<<<4096, 256>>>(W, b);
    prep_states<<<4096, 256>>>(x, h);
    rnn_persistent<<<128, 256, dynsmem>>>(out, h);
}

// round 14
// speedup vs baseline: 3.8998x; 1.0464x over previous
#include <cuda_runtime.h>
#include <cuda_fp16.h>
#include <mma.h>
#include <cstdint>

using namespace nvcuda;

#define NT    256
#define NB    64
#define NLAY  4
#define NHID  1024
#define NCH   16       // K chunks of 128 halfs per stage (K = 2048)

// ---------------- device global scratch ----------------
__device__ __half   g_W[(size_t)NLAY * 32 * 2048 * 64];   // [(l*32+s)*2048 + k][64]; cols 0-31 learn, 32-63 forget
__device__ float    g_br[NLAY * 2048];                    // bias, paired cols
__device__ __half   g_X[(size_t)NT * NB * 1024];          // x fp16, plain [t][r][k]
__device__ __half   g_act[(size_t)NLAY * 257 * NB * 1024];// [l][slot][r][jg]; slot0 = h_init, slot t+1 = h(t)
__device__ unsigned g_done[NLAY * NT];

// ---------------- helpers ----------------
__device__ __forceinline__ void cp16(uint32_t sdst, const void* gsrc) {
    asm volatile("cp.async.cg.shared.global [%0], [%1], 16;" :: "r"(sdst), "l"(gsrc));
}
// .noinc is load-bearing: the default form is count-neutral and deadlocks a
// barrier whose only arrivals are cp.async-tracked.
__device__ __forceinline__ void cp_mbar_arrive(uint32_t mbar) {
    asm volatile("cp.async.mbarrier.arrive.noinc.shared.b64 [%0];" :: "r"(mbar) : "memory");
}
__device__ __forceinline__ void mbar_init(uint32_t a, uint32_t cnt) {
    asm volatile("mbarrier.init.shared.b64 [%0], %1;" :: "r"(a), "r"(cnt) : "memory");
}
__device__ __forceinline__ void mbar_arrive(uint32_t a) {
    asm volatile("mbarrier.arrive.shared.b64 _, [%0];" :: "r"(a) : "memory");
}
__device__ __forceinline__ void mbar_wait(uint32_t a, uint32_t parity) {
    asm volatile(
        "{\n\t.reg .pred P;\n\tWL_%=: \n\t"
        "mbarrier.try_wait.parity.acquire.cta.shared::cta.b64 P, [%0], %1, 0x989680;\n\t"
        "@P bra.uni WD_%=;\n\tbra.uni WL_%=;\n\tWD_%=: \n\t}"
        :: "r"(a), "r"(parity) : "memory");
}
__device__ __forceinline__ void spin_ge(const unsigned* p, unsigned v) {
    unsigned x;
    do { asm volatile("ld.acquire.gpu.global.u32 %0, [%1];" : "=r"(x) : "l"(p) : "memory"); } while (x < v);
}
__device__ __forceinline__ float tanh_fast(float x) {
    float y; asm("tanh.approx.f32 %0, %1;" : "=f"(y) : "f"(x)); return y;
}

// ---------------- prep kernels ----------------
__global__ void prep_weights(const float* __restrict__ W, const float* __restrict__ b) {
    long long i0 = (long long)blockIdx.x * 256 + threadIdx.x;
    if (i0 < NLAY * NT) g_done[i0] = 0;
    if (i0 < NLAY * 2048) {
        int l = (int)(i0 >> 11), n = (int)(i0 & 2047);
        int s, c;
        if (n < NHID) { s = n >> 5; c = n & 31; }
        else          { s = (n - NHID) >> 5; c = 32 + ((n - NHID) & 31); }
        g_br[(l * 32 + s) * 64 + c] = b[i0];
    }
    const long long total = (long long)NLAY * 2048 * 2048;
    for (long long i = i0; i < total; i += (long long)gridDim.x * 256) {
        int n = (int)(i & 2047);
        int k = (int)((i >> 11) & 2047);
        int l = (int)(i >> 22);
        int s, c;
        if (n < NHID) { s = n >> 5; c = n & 31; }
        else          { s = (n - NHID) >> 5; c = 32 + ((n - NHID) & 31); }
        g_W[(((size_t)(l * 32 + s) * 2048 + k) << 6) + c] = __float2half(W[i]);
    }
}

__global__ void prep_states(const float* __restrict__ x, const float* __restrict__ h) {
    long long i0 = (long long)blockIdx.x * 256 + threadIdx.x;
    if (i0 < (long long)NLAY * NB * NHID) {   // h -> act[l][slot 0]
        int l = (int)(i0 >> 16);
        g_act[(size_t)l * 257 * 65536 + (i0 & 65535)] = __float2half(h[i0]);
    }
    const long long total = (long long)NT * NB * 1024;
    for (long long i = i0; i < total; i += (long long)gridDim.x * 256)
        g_X[i] = __float2half(x[i]);
}

// ---------------- main persistent kernel ----------------
// 128 blocks = 4 layers x 32 slices (64 paired cols each). 384 threads:
//   warps 0-7: wmma compute, K-SPLIT: warp w -> kk in [(w>>2)*4, +4), tile (mi,ni)
//              = ((w>>1)&1, w&1) of 32x32. Two partial-z buffers (one per k-group).
//   warps 8-11: cp.async producer + gate (gate sums both z partials).
#define AS_B  17408   // 64 x 136 halfs
#define WS_B  18432   // 128 x 72 halfs
#define ZS    4352    // 64 x 68 floats (one partial-z buffer)

__global__ void __launch_bounds__(384, 1) rnn_persistent(float* __restrict__ out, const float* __restrict__ h0) {
    extern __shared__ __align__(16) unsigned char dynsmem[];
    const uint32_t raw  = (uint32_t)__cvta_generic_to_shared(dynsmem);
    const uint32_t base = (raw + 1023u) & ~1023u;
    const uint32_t goff = base - raw;                 // generic-pointer offset of base

    const uint32_t full_mb  = base + 0;               // 4 x 8B
    const uint32_t free_mb  = base + 32;              // 4 x 8B
    const uint32_t zdone_mb = base + 64;              // 2 x 8B
    const uint32_t zfree_mb = base + 80;              // 2 x 8B
    const uint32_t As0 = base + 1024;                 // 4 x AS_B
    const uint32_t Ws0 = As0 + 4 * AS_B;              // 4 x WS_B
    __half* As_gen = (__half*)(dynsmem + goff + 1024);
    __half* Ws_gen = (__half*)(dynsmem + goff + 1024 + 4 * AS_B);
    // zbuf[tbuf 0/1][kgrp 0/1][64][68]
    float*  zbuf   = (float*)(dynsmem + goff + 1024 + 4 * AS_B + 4 * WS_B);

    const int tid = threadIdx.x;
    const int wid = tid >> 5;
    const int l = blockIdx.x >> 5;
    const int s = blockIdx.x & 31;

    if (tid == 0) {
        // full: 128 producer-thread .noinc arrivals; free: 256 compute threads;
        // zdone: 256 compute threads; zfree: 128 producer threads.
        for (int i = 0; i < 4; ++i) { mbar_init(full_mb + i * 8, 128); mbar_init(free_mb + i * 8, 256); }
        mbar_init(zdone_mb, 256); mbar_init(zdone_mb + 8, 256);
        mbar_init(zfree_mb, 128); mbar_init(zfree_mb + 8, 128);
    }
    __syncthreads();

    if (wid < 8) {
        // ================= compute: warps 0-7, K-split =================
        const int kgrp = wid >> 2;          // kk range [kgrp*4, kgrp*4+4)
        const int mi   = (wid >> 1) & 1;    // 32-row tile
        const int ni   = wid & 1;           // 32-col tile
        unsigned c = 0;
        for (int t = 0; t < NT; ++t) {
            wmma::fragment<wmma::accumulator, 16, 16, 16, float> acc[2][2];
#pragma unroll
            for (int i = 0; i < 2; ++i)
#pragma unroll
                for (int jj = 0; jj < 2; ++jj) wmma::fill_fragment(acc[i][jj], 0.f);

            for (int ch = 0; ch < NCH; ++ch, ++c) {
                const int slot = c & 3;
                const unsigned u = c >> 2;
                mbar_wait(full_mb + slot * 8, u & 1);
                const __half* as = As_gen + slot * (AS_B / 2);
                const __half* ws = Ws_gen + slot * (WS_B / 2);
#pragma unroll
                for (int k4 = 0; k4 < 4; ++k4) {
                    const int kk = kgrp * 4 + k4;
                    wmma::fragment<wmma::matrix_a, 16, 16, 16, __half, wmma::row_major> af0, af1;
                    wmma::fragment<wmma::matrix_b, 16, 16, 16, __half, wmma::row_major> bf0, bf1;
                    wmma::load_matrix_sync(af0, as + (mi * 32) * 136 + kk * 16, 136);
                    wmma::load_matrix_sync(af1, as + (mi * 32 + 16) * 136 + kk * 16, 136);
                    wmma::load_matrix_sync(bf0, ws + (kk * 16) * 72 + ni * 32, 72);
                    wmma::load_matrix_sync(bf1, ws + (kk * 16) * 72 + ni * 32 + 16, 72);
                    wmma::mma_sync(acc[0][0], af0, bf0, acc[0][0]);
                    wmma::mma_sync(acc[0][1], af0, bf1, acc[0][1]);
                    wmma::mma_sync(acc[1][0], af1, bf0, acc[1][0]);
                    wmma::mma_sync(acc[1][1], af1, bf1, acc[1][1]);
                }
                mbar_arrive(free_mb + slot * 8);
            }
            if (t >= 2) mbar_wait(zfree_mb + (t & 1) * 8, ((t - 2) >> 1) & 1);
            float* z = zbuf + (t & 1) * (2 * ZS) + kgrp * ZS;
#pragma unroll
            for (int i = 0; i < 2; ++i)
#pragma unroll
                for (int jj = 0; jj < 2; ++jj)
                    wmma::store_matrix_sync(z + (mi * 32 + i * 16) * 68 + ni * 32 + jj * 16,
                                            acc[i][jj], 68, wmma::mem_row_major);
            mbar_arrive(zdone_mb + (t & 1) * 8);
        }
    } else {
        // ================= producer + gate: warps 8-11 =================
        const int pid = tid - 256;                    // 0..127
        const int r   = pid >> 1;                     // gate row 0..63
        const int hf  = pid & 1;                      // col half
        const int j0  = hf * 16;
        const int jg0 = s * 32 + j0;
        const __half* Wbase = g_W + ((size_t)(l * 32 + s) << 17);

        float hreg[16], blv[16], bfv[16];
#pragma unroll
        for (int i = 0; i < 16; ++i) {
            blv[i]  = g_br[(l * 32 + s) * 64 + j0 + i];
            bfv[i]  = g_br[(l * 32 + s) * 64 + 32 + j0 + i];
            hreg[i] = h0[(size_t)(l * 64 + r) * 1024 + jg0 + i];
        }

        unsigned c = 0;
        auto produce = [&](const __half* asrc, int ch) {
            const int slot = c & 3;
            const unsigned u = c >> 2;
            if (u > 0) mbar_wait(free_mb + slot * 8, (u - 1) & 1);
            // A-side reads a 1024-wide source image at K offset (ch & 7)*128;
            // W-side indexes the full K=2048 directly (rows 1024+ = hidden weights).
            const int aoff = (ch & 7) * 128;
#pragma unroll
            for (int k8 = 0; k8 < 8; ++k8) {          // A: 64 x 128 halfs
                int i = pid + k8 * 128;
                int ar = i >> 4, c16 = i & 15;
                cp16(As0 + slot * AS_B + (ar * 136 + c16 * 8) * 2,
                     asrc + (size_t)ar * 1024 + aoff + c16 * 8);
            }
#pragma unroll
            for (int k8 = 0; k8 < 8; ++k8) {          // W: 128 x 64 halfs
                int i = pid + k8 * 128;
                int wr = i >> 3, c8 = i & 7;
                cp16(Ws0 + slot * WS_B + (wr * 72 + c8 * 8) * 2,
                     Wbase + (((size_t)(ch * 128 + wr)) << 6) + c8 * 8);
            }
            cp_mbar_arrive(full_mb + slot * 8);
            ++c;
        };
        auto produce_x = [&](int t) {                 // chunks 0-7: layer input at time t
            const __half* asrc = (l == 0) ? (g_X + (size_t)t * 65536)
                                          : (g_act + (((size_t)(l - 1) * 257 + t + 1) << 16));
            if (l > 0) spin_ge(&g_done[(l - 1) * NT + t], 32);
            for (int ch = 0; ch < 8; ++ch) produce(asrc, ch);
        };
        auto produce_h = [&](int t) {                 // chunks 8-15: h(t-1) = act[l][slot t]
            // Full 1024-wide K operand carries contributions from ALL 32
            // slice-blocks of this layer -> wait for the whole layer's gate at t-1.
            if (t > 0) spin_ge(&g_done[l * NT + t - 1], 32);
            const __half* asrc = g_act + (((size_t)l * 257 + t) << 16);
            for (int ch = 8; ch < 16; ++ch) produce(asrc, ch);
        };

        produce_x(0); produce_h(0);
        for (int t = 0; t < NT; ++t) {
            if (t + 1 < NT) produce_x(t + 1);         // overlap next stage's x-half with this gate

            mbar_wait(zdone_mb + (t & 1) * 8, (t >> 1) & 1);
            const float* z0 = zbuf + (t & 1) * (2 * ZS);
            const float* z1 = z0 + ZS;
            float zl[16], zf[16];
#pragma unroll
            for (int i = 0; i < 16; ++i) {
                zl[i] = z0[r * 68 + j0 + i]      + z1[r * 68 + j0 + i];
                zf[i] = z0[r * 68 + 32 + j0 + i] + z1[r * 68 + 32 + j0 + i];
            }
            mbar_arrive(zfree_mb + (t & 1) * 8);      // z buffers free for stage t+2

            __half* act = g_act + (((size_t)l * 257 + t + 1) << 16) + r * 1024 + jg0;
            float hv[16];
#pragma unroll
            for (int i = 0; i < 8; ++i) {
                float f0 = 1.f / (1.f + __expf(-(zf[2 * i]     + bfv[2 * i])));
                float f1 = 1.f / (1.f + __expf(-(zf[2 * i + 1] + bfv[2 * i + 1])));
                float h0v = fmaf(f0, hreg[2 * i],     (1.f - f0) * tanh_fast(zl[2 * i]     + blv[2 * i]));
                float h1v = fmaf(f1, hreg[2 * i + 1], (1.f - f1) * tanh_fast(zl[2 * i + 1] + blv[2 * i + 1]));
                hreg[2 * i] = h0v; hreg[2 * i + 1] = h1v;
                hv[2 * i] = h0v; hv[2 * i + 1] = h1v;
                *(__half2*)(act + 2 * i) = __halves2half2(__float2half(h0v), __float2half(h1v));
            }
            if (l == 3) {
                float4* ob = (float4*)(out + (size_t)(t * 64 + r) * 1024 + jg0);
#pragma unroll
                for (int q = 0; q < 4; ++q)
                    ob[q] = make_float4(hv[4 * q], hv[4 * q + 1], hv[4 * q + 2], hv[4 * q + 3]);
            }
            asm volatile("bar.sync 1, 128;" ::: "memory");   // gate warps only
            if (pid == 0) { __threadfence(); atomicAdd(&g_done[l * NT + t], 1u); }

            if (t + 1 < NT) produce_h(t + 1);         // waits whole-layer done(t) inside
        }
        // h_final appended after outputs
        float4* ob = (float4*)(out + (size_t)NT * NB * NHID + (size_t)(l * 64 + r) * 1024 + jg0);
#pragma unroll
        for (int q = 0; q < 4; ++q)
            ob[q] = make_float4(hreg[4 * q], hreg[4 * q + 1], hreg[4 * q + 2], hreg[4 * q + 3]);
    }
}

// ---------------- launch ----------------
extern "C" void kernel_launch(void* const* d_in, const int* in_sizes, int n_in,
                              void* d_out, int out_size) {
    const float* x = (const float*)d_in[0];
    const float* h = (const float*)d_in[1];
    const float* W = (const float*)d_in[2];
    const float* b = (const float*)d_in[3];
    float* out = (float*)d_out;

    // dyn smem: 1024 slack + 1024 mbars + 4*AS_B + 4*WS_B + 4*ZS*4 = 215040
    const int dynsmem = 1024 + 1024 + 4 * AS_B + 4 * WS_B + 4 * ZS * 4;
    static int attr_set = 0;
    if (!attr_set) {
        cudaFuncSetAttribute(rnn_persistent, cudaFuncAttributeMaxDynamicSharedMemorySize, dynsmem);
        attr_set = 1;
    }

    prep_weights<<<4096, 256>>>(W, b);
    prep_states<<<4096, 256>>>(x, h);
    rnn_persistent<<<128, 384, dynsmem>>>(out, h);
}